// round 5
// baseline (speedup 1.0000x reference)
#include <cuda_runtime.h>

#define KCLS 256
#define WARPS_PER_BLOCK 8
#define THREADS (WARPS_PER_BLOCK * 32)

__device__ __forceinline__ float ex2f(float a) {
    float r; asm("ex2.approx.f32 %0, %1;" : "=f"(r) : "f"(a)); return r;
}
__device__ __forceinline__ float rcpf(float a) {
    float r; asm("rcp.approx.f32 %0, %1;" : "=f"(r) : "f"(a)); return r;
}

// minBlocksPerSM=4 -> reg cap 64/thread: room for the full live set, no spills.
__global__ __launch_bounds__(THREADS, 4)
void dbf_kernel(const int* __restrict__ data,
                const float* __restrict__ t,
                const float4* __restrict__ noise,
                float4* __restrict__ out,
                int nrows)
{
    __shared__ __align__(16) float sg[KCLS];
    __shared__ __align__(16) float sh[KCLS];

    const int tid  = threadIdx.x;
    const int lane = tid & 31;
    const int warp = tid >> 5;

    // Closed-form Cholesky of C0 = (K+0.001) I - 11^T:
    //   T_k = a/(k-a), g_k = sqrt(a+T_k), h_k = T_k/g_k, a = K+0.001
    {
        const float ALPHA = 256.001f;
        float kf = (float)tid;
        float T  = ALPHA / (kf - ALPHA);
        float g  = sqrtf(ALPHA + T);
        sg[tid] = g;
        sh[tid] = T / g;
    }
    __syncthreads();

    const int row = blockIdx.x * WARPS_PER_BLOCK + warp;
    if (row >= nrows) return;

    const int kbase = lane * 8;

    // Per-row scalars (issue early)
    const float L2E = 1.4426950408889634f;
    const float tv  = __ldg(t + row);
    const int   x   = __ldg(data + row);

    // Noise loads (coalesced float4 x2)
    const float4* nrow = noise + (size_t)row * (KCLS / 4);
    float4 n0 = __ldg(nrow + lane * 2 + 0);
    float4 n1 = __ldg(nrow + lane * 2 + 1);

    float sb = fminf(tv, 1.0f - 1e-6f);
    sb = fmaxf(sb, 1e-10f);
    const float sb2 = sb * L2E;                 // sb * log2(e)
    const float kb2 = 256.0f * (sb * sb) * L2E; // K * beta * log2(e)
    // Row-uniform shift instead of exact max (softmax-invariant):
    // largest exponent = sb2*y - 40, overflow needs y > ~7.2 sigma; never.
    const float cofs = kb2 + 40.0f;

    // Fold g,h,v -> gv,hv immediately: v/g/h die, live set stays small.
    float gv[8], hv[8];
    {
        float4 ga = *(const float4*)&sg[kbase];
        float4 gb = *(const float4*)&sg[kbase + 4];
        float4 ha = *(const float4*)&sh[kbase];
        float4 hb = *(const float4*)&sh[kbase + 4];
        gv[0] = ga.x * n0.x;  hv[0] = ha.x * n0.x;
        gv[1] = ga.y * n0.y;  hv[1] = ha.y * n0.y;
        gv[2] = ga.z * n0.z;  hv[2] = ha.z * n0.z;
        gv[3] = ga.w * n0.w;  hv[3] = ha.w * n0.w;
        gv[4] = gb.x * n1.x;  hv[4] = hb.x * n1.x;
        gv[5] = gb.y * n1.y;  hv[5] = hb.y * n1.y;
        gv[6] = gb.z * n1.z;  hv[6] = hb.z * n1.z;
        gv[7] = gb.w * n1.w;  hv[7] = hb.w * n1.w;
    }

    // Lane total of h*v (tree order)
    float run = ((hv[0] + hv[1]) + (hv[2] + hv[3]))
              + ((hv[4] + hv[5]) + (hv[6] + hv[7]));

    // Warp inclusive scan of lane totals
    float inc = run;
    #pragma unroll
    for (int d = 1; d < 32; d <<= 1) {
        float nb = __shfl_up_sync(0xFFFFFFFFu, inc, d);
        if (lane >= d) inc += nb;
    }
    const float excl = inc - run;   // exclusive prefix

    // Fused prefix + logit + exp2:  e_i = 2^( sb2*(gv_i + prefix_i) + bias_i )
    float e[8];
    float run2 = excl;
    float s = 0.0f;
    #pragma unroll
    for (int i = 0; i < 8; i++) {
        float bias = (kbase + i == x) ? (kb2 - cofs) : -cofs;
        e[i] = ex2f(fmaf(sb2, gv[i] + run2, bias));
        run2 += hv[i];
        s += e[i];
    }

    // Warp sum (only cross-lane reduction left)
    #pragma unroll
    for (int d = 16; d >= 1; d >>= 1)
        s += __shfl_xor_sync(0xFFFFFFFFu, s, d);

    const float rr = rcpf(s);
    float4* orow = out + (size_t)row * (KCLS / 4);
    orow[lane * 2 + 0] = make_float4(e[0]*rr, e[1]*rr, e[2]*rr, e[3]*rr);
    orow[lane * 2 + 1] = make_float4(e[4]*rr, e[5]*rr, e[6]*rr, e[7]*rr);
}

extern "C" void kernel_launch(void* const* d_in, const int* in_sizes, int n_in,
                              void* d_out, int out_size)
{
    const int*    data  = (const int*)d_in[0];
    const float*  t     = (const float*)d_in[1];
    const float4* noise = (const float4*)d_in[2];
    float4*       out   = (float4*)d_out;

    const int nrows = in_sizes[0];   // B*S = 16384
    const int blocks = (nrows + WARPS_PER_BLOCK - 1) / WARPS_PER_BLOCK;
    dbf_kernel<<<blocks, THREADS>>>(data, t, noise, out, nrows);
}

// round 6
// speedup vs baseline: 1.1020x; 1.1020x over previous
#include <cuda_runtime.h>

#define KCLS 256
#define WARPS_PER_BLOCK 8
#define THREADS (WARPS_PER_BLOCK * 32)
#define BLOCKS_RESIDENT 592   // 4 blocks/SM * 148 SMs

__device__ __forceinline__ float ex2f(float a) {
    float r; asm("ex2.approx.f32 %0, %1;" : "=f"(r) : "f"(a)); return r;
}
__device__ __forceinline__ float rcpf(float a) {
    float r; asm("rcp.approx.f32 %0, %1;" : "=f"(r) : "f"(a)); return r;
}

__global__ __launch_bounds__(THREADS, 4)
void dbf_kernel(const int* __restrict__ data,
                const float* __restrict__ t,
                const float4* __restrict__ noise,
                float4* __restrict__ out,
                int nrows)
{
    __shared__ __align__(16) float sg[KCLS];
    __shared__ __align__(16) float sh[KCLS];

    const int tid  = threadIdx.x;
    const int lane = tid & 31;
    const int warp = tid >> 5;

    // Closed-form Cholesky of C0 = (K+0.001) I - 11^T:
    //   T_k = a/(k-a), g_k = sqrt(a+T_k), h_k = T_k/g_k, a = K+0.001
    {
        const float ALPHA = 256.001f;
        float kf = (float)tid;
        float T  = ALPHA / (kf - ALPHA);
        float gg = sqrtf(ALPHA + T);
        sg[tid] = gg;
        sh[tid] = T / gg;
    }
    __syncthreads();

    const int kbase = lane * 8;

    // Hoist g/h into registers once per warp (amortized over the row loop)
    float4 ga = *(const float4*)&sg[kbase];
    float4 gb = *(const float4*)&sg[kbase + 4];
    float4 ha = *(const float4*)&sh[kbase];
    float4 hb = *(const float4*)&sh[kbase + 4];

    const float L2E = 1.4426950408889634f;
    const int stride = gridDim.x * WARPS_PER_BLOCK;

    int row = blockIdx.x * WARPS_PER_BLOCK + warp;
    if (row >= nrows) return;

    // Prime the pipeline: current row's loads in flight
    float tv = __ldg(t + row);
    int   x  = __ldg(data + row);
    const float4* nrow = noise + (size_t)row * (KCLS / 4) + lane * 2;
    float4 n0 = __ldg(nrow + 0);
    float4 n1 = __ldg(nrow + 1);

    while (true) {
        // ---- Prefetch next row before touching current data ----
        const int  rnext = row + stride;
        const bool has_next = rnext < nrows;
        float tv_n; int x_n; float4 m0, m1;
        if (has_next) {
            tv_n = __ldg(t + rnext);
            x_n  = __ldg(data + rnext);
            const float4* nn = noise + (size_t)rnext * (KCLS / 4) + lane * 2;
            m0 = __ldg(nn + 0);
            m1 = __ldg(nn + 1);
        }

        // ---- Compute current row ----
        float sb = fminf(tv, 1.0f - 1e-6f);
        sb = fmaxf(sb, 1e-10f);
        const float sb2 = sb * L2E;                 // sb * log2(e)
        const float kb2 = 256.0f * (sb * sb) * L2E; // K*beta*log2(e)
        // Row-uniform shift instead of exact max (softmax-invariant):
        // largest exponent = sb2*y - 40; overflow needs y > ~7.2 sigma.
        const float cofs = kb2 + 40.0f;

        float gv[8], hv[8];
        gv[0] = ga.x * n0.x;  hv[0] = ha.x * n0.x;
        gv[1] = ga.y * n0.y;  hv[1] = ha.y * n0.y;
        gv[2] = ga.z * n0.z;  hv[2] = ha.z * n0.z;
        gv[3] = ga.w * n0.w;  hv[3] = ha.w * n0.w;
        gv[4] = gb.x * n1.x;  hv[4] = hb.x * n1.x;
        gv[5] = gb.y * n1.y;  hv[5] = hb.y * n1.y;
        gv[6] = gb.z * n1.z;  hv[6] = hb.z * n1.z;
        gv[7] = gb.w * n1.w;  hv[7] = hb.w * n1.w;

        // Lane total of h*v (tree order)
        float run = ((hv[0] + hv[1]) + (hv[2] + hv[3]))
                  + ((hv[4] + hv[5]) + (hv[6] + hv[7]));

        // Warp inclusive scan of lane totals
        float inc = run;
        #pragma unroll
        for (int d = 1; d < 32; d <<= 1) {
            float nb = __shfl_up_sync(0xFFFFFFFFu, inc, d);
            if (lane >= d) inc += nb;
        }
        float run2 = inc - run;   // exclusive prefix

        // Fused prefix + logit + exp2
        float e[8];
        float s = 0.0f;
        #pragma unroll
        for (int i = 0; i < 8; i++) {
            float bias = (kbase + i == x) ? (kb2 - cofs) : -cofs;
            e[i] = ex2f(fmaf(sb2, gv[i] + run2, bias));
            run2 += hv[i];
            s += e[i];
        }

        // Warp sum
        #pragma unroll
        for (int d = 16; d >= 1; d >>= 1)
            s += __shfl_xor_sync(0xFFFFFFFFu, s, d);

        const float rr = rcpf(s);
        float4* orow = out + (size_t)row * (KCLS / 4) + lane * 2;
        orow[0] = make_float4(e[0]*rr, e[1]*rr, e[2]*rr, e[3]*rr);
        orow[1] = make_float4(e[4]*rr, e[5]*rr, e[6]*rr, e[7]*rr);

        // ---- Rotate pipeline ----
        if (!has_next) break;
        row = rnext;
        tv = tv_n; x = x_n; n0 = m0; n1 = m1;
    }
}

extern "C" void kernel_launch(void* const* d_in, const int* in_sizes, int n_in,
                              void* d_out, int out_size)
{
    const int*    data  = (const int*)d_in[0];
    const float*  t     = (const float*)d_in[1];
    const float4* noise = (const float4*)d_in[2];
    float4*       out   = (float4*)d_out;

    const int nrows = in_sizes[0];   // B*S = 16384
    int blocks = (nrows + WARPS_PER_BLOCK - 1) / WARPS_PER_BLOCK;
    if (blocks > BLOCKS_RESIDENT) blocks = BLOCKS_RESIDENT;
    dbf_kernel<<<blocks, THREADS>>>(data, t, noise, out, nrows);
}